// round 16
// baseline (speedup 1.0000x reference)
#include <cuda_runtime.h>
#include <cuda_fp16.h>
#include <cuda_bf16.h>
#include <cstdint>

// int4 weight-only quantized GEMV on GB300.
// Logical: A [1, K=8192], B int32 [N, K/2] (one byte per int32, two nibbles,
// low nibble = even k), scalesAndZeros [N, K/32, 2], out [1, N].
// The harness transports fp16 tensors as float32 (exact upcast, low 13
// mantissa bits zero) — detected at runtime; fp16/bf16 fallbacks kept.

#define K_DIM   8192
#define KH      (K_DIM / 2)      // 4096 int32 words per row
#define KH4     (KH / 4)         // 1024 uint4 per row
#define NGROUP  (K_DIM / 32)     // 256 groups per row
#define WARPS   8
#define THREADS (WARPS * 32)
#define ROWS    2                // N-rows per warp
#define STAGES  (KH4 / 128)      // 8 stages: warp eats 128 uint4/row/stage

#define MODE_FP16 0
#define MODE_FP32 1
#define MODE_BF16 2

__device__ int g_mode;

// Dtype probe over the first 4096 32-bit words of A.
// FP32-from-fp16 signature: low 13 mantissa bits of every word are zero.
// Genuine fp16/bf16 data (two values/word) has random bits 0-12.
// fp16 vs bf16 fallback: max |halfword as fp16| (fp16 N(0,1) max ~4.1;
// bf16 bits as fp16 bounded ~2.3; threshold 3.0 = 0x4200).
__global__ void probe_kernel(const uint32_t* __restrict__ A)
{
    __shared__ int lo13_nonzero;
    __shared__ int maxmag;
    if (threadIdx.x == 0) { lo13_nonzero = 0; maxmag = 0; }
    __syncthreads();

    int nz = 0, lmax = 0;
    for (int i = threadIdx.x; i < 4096; i += THREADS) {
        uint32_t w = A[i];
        if (w & 0x1FFFu) nz++;
        int m0 = (int)(w & 0x7FFFu);
        int m1 = (int)((w >> 16) & 0x7FFFu);
        lmax = max(lmax, max(m0, m1));
    }
    if (nz) atomicAdd(&lo13_nonzero, nz);
    atomicMax(&maxmag, lmax);
    __syncthreads();

    if (threadIdx.x == 0) {
        if (lo13_nonzero == 0)      g_mode = MODE_FP32;
        else if (maxmag > 0x4200)   g_mode = MODE_FP16;
        else                        g_mode = MODE_BF16;
    }
}

// Load one (scale, zero) pair for group g of a row, packed as (half s | half z)
// in a single 32-bit register. Lane-coalesced when g = base + lane.
template<int MODE>
__device__ __forceinline__ uint32_t load_sz_packed(const void* __restrict__ SZ,
                                                   size_t row, int g)
{
    if (MODE == MODE_FP32) {
        float2 f = __ldcs(&reinterpret_cast<const float2*>(SZ)[row * NGROUP + g]);
        half2 h = __floats2half2_rn(f.x, f.y);   // exact for fp16-origin data
        return *reinterpret_cast<uint32_t*>(&h);
    } else if (MODE == MODE_BF16) {
        uint32_t w = __ldcs(&reinterpret_cast<const uint32_t*>(SZ)[row * NGROUP + g]);
        uint32_t lo = w << 16, hi = w & 0xFFFF0000u;
        half2 h = __floats2half2_rn(__uint_as_float(lo), __uint_as_float(hi));
        return *reinterpret_cast<uint32_t*>(&h);
    } else {
        return __ldcs(&reinterpret_cast<const uint32_t*>(SZ)[row * NGROUP + g]);
    }
}

// 4 half2 dequant+dot chain for one uint4 (8 weights), flushed to fp32.
__device__ __forceinline__ void dot_u4(uint4 bv, uint4 av, half2 s2, half2 z2,
                                       half2 c1032, float2& facc)
{
    uint32_t v, hb; half2 h2, d2, w2, a2, acc2;

    v = (uint32_t)bv.x;
    hb = ((v & 0xFu) | 0x64006400u) | ((v << 12) & 0x000F0000u);
    h2 = *reinterpret_cast<half2*>(&hb);
    d2 = __hsub2(h2, c1032);                 // exact (q - 8), Sterbenz
    w2 = __hfma2(d2, s2, z2);
    a2 = *reinterpret_cast<half2*>(&av.x);
    acc2 = __hmul2(a2, w2);

    v = (uint32_t)bv.y;
    hb = ((v & 0xFu) | 0x64006400u) | ((v << 12) & 0x000F0000u);
    h2 = *reinterpret_cast<half2*>(&hb);
    d2 = __hsub2(h2, c1032);
    w2 = __hfma2(d2, s2, z2);
    a2 = *reinterpret_cast<half2*>(&av.y);
    acc2 = __hfma2(a2, w2, acc2);

    v = (uint32_t)bv.z;
    hb = ((v & 0xFu) | 0x64006400u) | ((v << 12) & 0x000F0000u);
    h2 = *reinterpret_cast<half2*>(&hb);
    d2 = __hsub2(h2, c1032);
    w2 = __hfma2(d2, s2, z2);
    a2 = *reinterpret_cast<half2*>(&av.z);
    acc2 = __hfma2(a2, w2, acc2);

    v = (uint32_t)bv.w;
    hb = ((v & 0xFu) | 0x64006400u) | ((v << 12) & 0x000F0000u);
    h2 = *reinterpret_cast<half2*>(&hb);
    d2 = __hsub2(h2, c1032);
    w2 = __hfma2(d2, s2, z2);
    a2 = *reinterpret_cast<half2*>(&av.w);
    acc2 = __hfma2(a2, w2, acc2);

    float2 f = __half22float2(acc2);
    facc.x += f.x;
    facc.y += f.y;
}

// Coalesced, register-double-buffered mainloop. Per stage, per row:
// 4 fully-coalesced LDG.128 (lane reads uint4 index stage*128 + j*32 + lane)
// + 1 coalesced packed-scale LDG for the stage's 32 groups. The NEXT stage's
// loads are issued before the current stage's compute, so each warp keeps
// ~4 KB continuously in flight (sustained MLP; fits the 128-reg budget of
// __launch_bounds__(256,2), unlike the R13 attempt at 40 regs).
template<int MODE>
__device__ __forceinline__ void mainloop(const uint4* __restrict__ B0,
                                         const uint4* __restrict__ B1,
                                         const void* __restrict__ SZ, size_t n0,
                                         const uint4* __restrict__ As4, int lane,
                                         float2* facc)
{
    const half2 c1032 = __half2half2(__ushort_as_half(0x6408));  // 1032.0

    uint4    cb[ROWS][4];
    uint32_t cp[ROWS];

    // prologue: stage 0 loads
    #pragma unroll
    for (int j = 0; j < 4; ++j) {
        cb[0][j] = __ldcs(&B0[lane + j * 32]);
        cb[1][j] = __ldcs(&B1[lane + j * 32]);
    }
    cp[0] = load_sz_packed<MODE>(SZ, n0,     lane);
    cp[1] = load_sz_packed<MODE>(SZ, n0 + 1, lane);

    #pragma unroll
    for (int sup = 0; sup < STAGES; ++sup) {
        uint4    nb[ROWS][4];
        uint32_t np[ROWS];

        // ---- prefetch next stage BEFORE computing current ----
        if (sup + 1 < STAGES) {
            const int nbase = (sup + 1) * 128 + lane;
            #pragma unroll
            for (int j = 0; j < 4; ++j) {
                nb[0][j] = __ldcs(&B0[nbase + j * 32]);
                nb[1][j] = __ldcs(&B1[nbase + j * 32]);
            }
            np[0] = load_sz_packed<MODE>(SZ, n0,     (sup + 1) * 32 + lane);
            np[1] = load_sz_packed<MODE>(SZ, n0 + 1, (sup + 1) * 32 + lane);
        }

        // ---- compute current stage (smem av shared across rows) ----
        const int base = sup * 128 + lane;
        #pragma unroll
        for (int j = 0; j < 4; ++j) {
            uint4 av = As4[base + j * 32];        // LDS.128, conflict-free
            const int src = j * 8 + (lane >> 2);  // group owner lane
            #pragma unroll
            for (int r = 0; r < ROWS; ++r) {
                uint32_t p = __shfl_sync(0xFFFFFFFFu, cp[r], src);
                half2 szh = *reinterpret_cast<half2*>(&p);
                half2 s2 = __half2half2(__low2half(szh));
                half2 z2 = __half2half2(__high2half(szh));
                dot_u4(cb[r][j], av, s2, z2, c1032, facc[r]);
            }
        }

        // ---- rotate ----
        if (sup + 1 < STAGES) {
            #pragma unroll
            for (int j = 0; j < 4; ++j) {
                cb[0][j] = nb[0][j];
                cb[1][j] = nb[1][j];
            }
            cp[0] = np[0];
            cp[1] = np[1];
        }
    }
}

__global__ __launch_bounds__(THREADS, 2)
void gemv_int4_kernel(const void* __restrict__ Aptr,
                      const int*  __restrict__ B,
                      const void* __restrict__ SZptr,
                      void*       __restrict__ outptr,
                      int N)
{
    const int mode = g_mode;

    // A staged as 4096 packed half2 pairs; plain layout (coalesced mainloop
    // reads are naturally conflict-free).
    __shared__ __align__(16) uint32_t a_sm[KH];

    if (mode == MODE_FP32) {
        const float2* Av = reinterpret_cast<const float2*>(Aptr);
        for (int i = threadIdx.x; i < KH; i += THREADS) {
            float2 v = Av[i];
            half2 h = __floats2half2_rn(v.x, v.y);
            a_sm[i] = *reinterpret_cast<uint32_t*>(&h);
        }
    } else if (mode == MODE_BF16) {
        const uint32_t* Av = reinterpret_cast<const uint32_t*>(Aptr);
        for (int i = threadIdx.x; i < KH; i += THREADS) {
            uint32_t w = Av[i];
            uint32_t lo = w << 16, hi = w & 0xFFFF0000u;   // bf16 -> fp32 shift
            half2 h = __floats2half2_rn(__uint_as_float(lo), __uint_as_float(hi));
            a_sm[i] = *reinterpret_cast<uint32_t*>(&h);
        }
    } else { // MODE_FP16
        const uint32_t* Av = reinterpret_cast<const uint32_t*>(Aptr);
        for (int i = threadIdx.x; i < KH; i += THREADS)
            a_sm[i] = Av[i];
    }
    __syncthreads();

    const int warp = threadIdx.x >> 5;
    const int lane = threadIdx.x & 31;
    const int n0 = (blockIdx.x * WARPS + warp) * ROWS;
    if (n0 >= N) return;

    const uint4* B0  = reinterpret_cast<const uint4*>(B + (size_t)n0 * KH);
    const uint4* B1  = reinterpret_cast<const uint4*>(B + (size_t)(n0 + 1) * KH);
    const uint4* As4 = reinterpret_cast<const uint4*>(a_sm);

    float2 facc[ROWS];
    #pragma unroll
    for (int r = 0; r < ROWS; ++r) facc[r] = make_float2(0.f, 0.f);

    if (mode == MODE_FP32)
        mainloop<MODE_FP32>(B0, B1, SZptr, (size_t)n0, As4, lane, facc);
    else if (mode == MODE_BF16)
        mainloop<MODE_BF16>(B0, B1, SZptr, (size_t)n0, As4, lane, facc);
    else
        mainloop<MODE_FP16>(B0, B1, SZptr, (size_t)n0, As4, lane, facc);

    float s[ROWS];
    #pragma unroll
    for (int r = 0; r < ROWS; ++r) s[r] = facc[r].x + facc[r].y;

    #pragma unroll
    for (int off = 16; off > 0; off >>= 1) {
        #pragma unroll
        for (int r = 0; r < ROWS; ++r)
            s[r] += __shfl_xor_sync(0xFFFFFFFFu, s[r], off);
    }

    if (lane == 0) {
        #pragma unroll
        for (int r = 0; r < ROWS; ++r) {
            if (mode == MODE_FP32)
                reinterpret_cast<float*>(outptr)[n0 + r] = s[r];
            else if (mode == MODE_BF16)
                reinterpret_cast<__nv_bfloat16*>(outptr)[n0 + r] = __float2bfloat16(s[r]);
            else
                reinterpret_cast<__half*>(outptr)[n0 + r] = __float2half(s[r]);
        }
    }
}

extern "C" void kernel_launch(void* const* d_in, const int* in_sizes, int n_in,
                              void* d_out, int out_size)
{
    // Identify tensors by element count (ordering-proof):
    //   A = 8192, B = N*K/2 (largest), SZ = N*K/32*2
    int iA = -1, iB = -1, iS = -1;
    for (int i = 0; i < n_in; ++i) {
        if      (in_sizes[i] == K_DIM) iA = i;
        else if (iB < 0 || in_sizes[i] > in_sizes[iB]) { if (iB >= 0) iS = iB; iB = i; }
        else iS = i;
    }
    if (iA < 0 || iB < 0 || iS < 0) { iA = 0; iB = 1; iS = 2; }

    const void* A  = d_in[iA];
    const int*  B  = (const int*)d_in[iB];
    const void* SZ = d_in[iS];

    const int N = in_sizes[iB] / KH;

    probe_kernel<<<1, THREADS>>>((const uint32_t*)A);

    const int rows_per_block = WARPS * ROWS;
    const int grid = (N + rows_per_block - 1) / rows_per_block;
    gemv_int4_kernel<<<grid, THREADS>>>(A, B, SZ, d_out, N);
}